// round 6
// baseline (speedup 1.0000x reference)
#include <cuda_runtime.h>
#include <math.h>

#define BATCH 8
#define SEQ   1024
#define HID   768
#define INNER 64
#define ENT   9
#define NEGC  1000000000000.0f

// ---------------- scratch (device globals; no allocation allowed) ----------------
__device__ float g_q[BATCH * SEQ * INNER];       // rope'd q, [row][64]
__device__ float g_k[BATCH * SEQ * INNER];       // rope'd k, [row][64]
__device__ float g_be[BATCH * ENT * SEQ];        // bias even (col/n bias)
__device__ float g_bo[BATCH * ENT * SEQ];        // bias odd  (row/m bias)

// =====================================================================
// Fused Kernel A:
//   blocks 0..127    -> proj GEMM (BM=64, BN=128, BK=16, micro 8x4) + RoPE
//   blocks 128..1151 -> bias GEMM, warp-per-row, NO smem (shfl reduction)
// Dynamic smem = proj layout only: (16*68 + 16*128)*4 = 12544 B.
// =====================================================================

__device__ __forceinline__ void proj_body(float* smem,
                                          const float* __restrict__ X,
                                          const float* __restrict__ w1,
                                          const float* __restrict__ b1,
                                          int blk)
{
    float* As = smem;               // [16][68]  (k-major, padded)
    float* Bs = smem + 16 * 68;     // [16][128]

    const int tid = threadIdx.x;
    const int rowBase = blk * 64;

    const int lm = tid >> 2;            // 0..63
    const int lk = (tid & 3) << 2;      // 0,4,8,12
    const float* Xrow = X + (size_t)(rowBase + lm) * HID + lk;

    const int nthr = tid & 31;          // pair index i
    const int mthr = tid >> 5;
    const int n0 = nthr << 2;
    const int m0 = mthr << 3;

    float acc[8][4];
#pragma unroll
    for (int mi = 0; mi < 8; ++mi)
#pragma unroll
        for (int ni = 0; ni < 4; ++ni) acc[mi][ni] = 0.f;

    const int wi0 = tid, wi1 = tid + 256;
    float4 xa  = *(const float4*)(Xrow);
    float4 wv0 = *(const float4*)&w1[(wi0 >> 5) * 128 + (wi0 & 31) * 4];
    float4 wv1 = *(const float4*)&w1[(wi1 >> 5) * 128 + (wi1 & 31) * 4];

    for (int kc = 0; kc < HID / 16; ++kc) {
        __syncthreads();
        As[(lk + 0) * 68 + lm] = xa.x;
        As[(lk + 1) * 68 + lm] = xa.y;
        As[(lk + 2) * 68 + lm] = xa.z;
        As[(lk + 3) * 68 + lm] = xa.w;
        *(float4*)&Bs[(wi0 >> 5) * 128 + (wi0 & 31) * 4] = wv0;
        *(float4*)&Bs[(wi1 >> 5) * 128 + (wi1 & 31) * 4] = wv1;
        __syncthreads();

        if (kc + 1 < HID / 16) {
            xa  = *(const float4*)(Xrow + (kc + 1) * 16);
            wv0 = *(const float4*)&w1[((kc + 1) * 16 + (wi0 >> 5)) * 128 + (wi0 & 31) * 4];
            wv1 = *(const float4*)&w1[((kc + 1) * 16 + (wi1 >> 5)) * 128 + (wi1 & 31) * 4];
        }

#pragma unroll
        for (int kk = 0; kk < 16; ++kk) {
            float4 a0 = *(const float4*)(&As[kk * 68 + m0]);
            float4 a1 = *(const float4*)(&As[kk * 68 + m0 + 4]);
            float4 bv = *(const float4*)(&Bs[kk * 128 + n0]);
            float am[8] = {a0.x, a0.y, a0.z, a0.w, a1.x, a1.y, a1.z, a1.w};
            float bn[4] = {bv.x, bv.y, bv.z, bv.w};
#pragma unroll
            for (int mi = 0; mi < 8; ++mi)
#pragma unroll
                for (int ni = 0; ni < 4; ++ni)
                    acc[mi][ni] = fmaf(am[mi], bn[ni], acc[mi][ni]);
        }
    }

    const int i = nthr;
    const float invf = powf(10000.0f, -(float)i * (1.0f / 32.0f));
    const float4 b1v = *(const float4*)&b1[n0];

#pragma unroll
    for (int mi = 0; mi < 8; ++mi) {
        const int r = rowBase + m0 + mi;
        const int pos = r & (SEQ - 1);
        float sv, cv;
        sincosf((float)pos * invf, &sv, &cv);
        const float q0 = acc[mi][0] + b1v.x;   // proj col 4i   -> q[2i]
        const float k0 = acc[mi][1] + b1v.y;   // proj col 4i+1 -> k[2i]
        const float q1 = acc[mi][2] + b1v.z;   // proj col 4i+2 -> q[2i+1]
        const float k1 = acc[mi][3] + b1v.w;   // proj col 4i+3 -> k[2i+1]
        float2 qo = make_float2(fmaf(q0, cv, -q1 * sv), fmaf(q1, cv, q0 * sv));
        float2 ko = make_float2(fmaf(k0, cv, -k1 * sv), fmaf(k1, cv, k0 * sv));
        ((float2*)g_q)[(r << 5) + i] = qo;
        ((float2*)g_k)[(r << 5) + i] = ko;
    }
}

// bias: warp-per-row, no smem. Each lane accumulates 18 partials over k=lane+32*i,
// then butterfly-reduce; lane 0 writes all 18 scattered outputs.
__device__ __forceinline__ void bias_body(const float* __restrict__ X,
                                          const float* __restrict__ w2,
                                          const float* __restrict__ b2,
                                          int blk)
{
    const int tid = threadIdx.x;
    const int w = tid >> 5;
    const int lane = tid & 31;
    const int row = blk * 8 + w;                 // 1024 blocks x 8 rows = 8192

    const float* xr = X + (size_t)row * HID;

    float acc[18];
#pragma unroll
    for (int e = 0; e < 18; ++e) acc[e] = 0.f;

#pragma unroll 2
    for (int i = 0; i < HID / 32; ++i) {
        const int k = i * 32 + lane;
        const float xv = __ldg(&xr[k]);
        const float* wr = &w2[k * 18];
#pragma unroll
        for (int e = 0; e < 18; ++e) acc[e] = fmaf(xv, __ldg(&wr[e]), acc[e]);
    }

#pragma unroll
    for (int off = 16; off > 0; off >>= 1)
#pragma unroll
        for (int e = 0; e < 18; ++e)
            acc[e] += __shfl_xor_sync(0xffffffffu, acc[e], off);

    if (lane == 0) {
        const int bb = row >> 10, nn = row & (SEQ - 1);
#pragma unroll
        for (int e = 0; e < 18; ++e) {
            const float val = (acc[e] + b2[e]) * 0.5f;
            const int h = e >> 1;
            if ((e & 1) == 0) g_be[(bb * ENT + h) * SEQ + nn] = val;
            else              g_bo[(bb * ENT + h) * SEQ + nn] = val;
        }
    }
}

__global__ __launch_bounds__(256) void k_projbias(const float* __restrict__ X,
                                                  const float* __restrict__ w1,
                                                  const float* __restrict__ b1,
                                                  const float* __restrict__ w2,
                                                  const float* __restrict__ b2)
{
    extern __shared__ __align__(16) float smem[];
    const int bx = blockIdx.x;
    if (bx < 128) proj_body(smem, X, w1, b1, bx);
    else          bias_body(X, w2, b2, bx - 128);
}

// =====================================================================
// Kernel B: out[b,e,m,n] = (qk/8)*mr*mc + (negr*mc + negc + tril) + mr*mc*(be+bo)
// Tile: 128m x 64n, 256 threads, micro-tile 8m x 4n. Streaming stores (__stcs).
// =====================================================================
__global__ __launch_bounds__(256, 3) void k_out(const float* __restrict__ mask,
                                                float* __restrict__ out)
{
    __shared__ __align__(16) float qt[32 * 132];  // [d][m], stride 132
    __shared__ __align__(16) float kt[32 * 68];   // [d][n], stride 68
    __shared__ __align__(16) float bes[ENT * 64];
    __shared__ __align__(16) float bos[ENT * 128];
    __shared__ __align__(16) float mrow[128];
    __shared__ __align__(16) float mcol[64];

    const int tid = threadIdx.x;
    const int nBase = blockIdx.x * 64;
    const int mBase = blockIdx.y * 128;
    const int b = blockIdx.z;
    const int bOff = b * SEQ;

    const int n0 = (tid & 15) << 2;               // 0..60
    const int m0 = (tid >> 4) << 3;               // 0..120

    for (int i = tid; i < ENT * 64; i += 256)
        bes[i] = g_be[(b * ENT + (i >> 6)) * SEQ + nBase + (i & 63)];
    for (int i = tid; i < ENT * 128; i += 256)
        bos[i] = g_bo[(b * ENT + (i >> 7)) * SEQ + mBase + (i & 127)];
    for (int i = tid; i < 128; i += 256) mrow[i] = mask[b * SEQ + mBase + i];
    if (tid < 64) mcol[tid] = mask[b * SEQ + nBase + tid];

    float acc[8][4];
#pragma unroll
    for (int mi = 0; mi < 8; ++mi)
#pragma unroll
        for (int ni = 0; ni < 4; ++ni) acc[mi][ni] = 0.f;

    for (int ch = 0; ch < 2; ++ch) {
        __syncthreads();
        // q tile transposed: m-fast mapping -> conflict-free STS
        for (int i = tid; i < 128 * 8; i += 256) {
            int m = i & 127, d4 = (i >> 7) << 2;
            float4 v = *(const float4*)&g_q[((size_t)(bOff + mBase + m) << 6) + ch * 32 + d4];
            qt[(d4 + 0) * 132 + m] = v.x;
            qt[(d4 + 1) * 132 + m] = v.y;
            qt[(d4 + 2) * 132 + m] = v.z;
            qt[(d4 + 3) * 132 + m] = v.w;
        }
        // k tile transposed: n-fast mapping
        for (int i = tid; i < 64 * 8; i += 256) {
            int n = i & 63, d4 = (i >> 6) << 2;
            float4 v = *(const float4*)&g_k[((size_t)(bOff + nBase + n) << 6) + ch * 32 + d4];
            kt[(d4 + 0) * 68 + n] = v.x;
            kt[(d4 + 1) * 68 + n] = v.y;
            kt[(d4 + 2) * 68 + n] = v.z;
            kt[(d4 + 3) * 68 + n] = v.w;
        }
        __syncthreads();

#pragma unroll 8
        for (int d = 0; d < 32; ++d) {
            float4 kv = *(const float4*)&kt[d * 68 + n0];
            float4 q0 = *(const float4*)&qt[d * 132 + m0];
            float4 q1 = *(const float4*)&qt[d * 132 + m0 + 4];
            float qv[8] = {q0.x, q0.y, q0.z, q0.w, q1.x, q1.y, q1.z, q1.w};
#pragma unroll
            for (int mi = 0; mi < 8; ++mi) {
                acc[mi][0] = fmaf(qv[mi], kv.x, acc[mi][0]);
                acc[mi][1] = fmaf(qv[mi], kv.y, acc[mi][1]);
                acc[mi][2] = fmaf(qv[mi], kv.z, acc[mi][2]);
                acc[mi][3] = fmaf(qv[mi], kv.w, acc[mi][3]);
            }
        }
    }

    // ---- epilogue: fold scale, masks, tril into acc ----
    float mr[8];
#pragma unroll
    for (int mi = 0; mi < 8; ++mi) mr[mi] = mrow[m0 + mi];
    float4 mcv = *(const float4*)&mcol[n0];
    float mcs[4] = {mcv.x, mcv.y, mcv.z, mcv.w};

#pragma unroll
    for (int mi = 0; mi < 8; ++mi) {
        const float negr = -NEGC * (1.0f - mr[mi]);
        const int m = mBase + m0 + mi;
#pragma unroll
        for (int ni = 0; ni < 4; ++ni) {
            const float mc = mcs[ni];
            const float negc = -NEGC * (1.0f - mc);
            const int n = nBase + n0 + ni;
            const float t = (n < m) ? -NEGC : 0.0f;
            const float p = acc[mi][ni] * 0.125f * mr[mi];
            acc[mi][ni] = fmaf(p, mc, fmaf(negr, mc, negc + t));
        }
    }

    // ---- 9 output planes, streaming stores ----
#pragma unroll
    for (int e = 0; e < ENT; ++e) {
        float4 bev = *(const float4*)&bes[e * 64 + n0];
        float beA[4] = {bev.x, bev.y, bev.z, bev.w};
        const size_t planeRow = (size_t)(b * ENT + e) << 10;
#pragma unroll
        for (int mi = 0; mi < 8; ++mi) {
            const float bo = bos[e * 128 + m0 + mi];
            const float c1 = mr[mi] * bo;
            float4 o;
            o.x = fmaf(mcs[0], fmaf(mr[mi], beA[0], c1), acc[mi][0]);
            o.y = fmaf(mcs[1], fmaf(mr[mi], beA[1], c1), acc[mi][1]);
            o.z = fmaf(mcs[2], fmaf(mr[mi], beA[2], c1), acc[mi][2]);
            o.w = fmaf(mcs[3], fmaf(mr[mi], beA[3], c1), acc[mi][3]);
            __stcs((float4*)&out[((planeRow + mBase + m0 + mi) << 10) + nBase + n0], o);
        }
    }
}

// =====================================================================
extern "C" void kernel_launch(void* const* d_in, const int* in_sizes, int n_in,
                              void* d_out, int out_size)
{
    const float* X    = (const float*)d_in[0];   // (8,1024,768)
    const float* mask = (const float*)d_in[1];   // (8,1024)
    const float* w1   = (const float*)d_in[2];   // (768,128)
    const float* b1   = (const float*)d_in[3];   // (128,)
    const float* w2   = (const float*)d_in[4];   // (768,18)
    const float* b2   = (const float*)d_in[5];   // (18,)
    float* out = (float*)d_out;                  // (8,9,1024,1024)

    // dynamic smem = proj layout only: (16*68 + 16*128) floats = 12544 B
    const int smemBytes = (16 * 68 + 16 * 128) * 4;
    k_projbias<<<1152, 256, smemBytes>>>(X, w1, b1, w2, b2);
    k_out<<<dim3(16, 8, 8), 256>>>(mask, out);
}

// round 7
// speedup vs baseline: 1.1049x; 1.1049x over previous
#include <cuda_runtime.h>
#include <math.h>

#define BATCH 8
#define SEQ   1024
#define HID   768
#define INNER 64
#define ENT   9
#define NEGC  1000000000000.0f

// ---------------- scratch (device globals; no allocation allowed) ----------------
__device__ float g_q[BATCH * SEQ * INNER];       // rope'd q, [row][64]
__device__ float g_k[BATCH * SEQ * INNER];       // rope'd k, [row][64]
__device__ float g_be[BATCH * ENT * SEQ];        // bias even (col/n bias)
__device__ float g_bo[BATCH * ENT * SEQ];        // bias odd  (row/m bias)

// =====================================================================
// Fused Kernel A:
//   blocks 0..127   -> proj GEMM (BM=64, BN=128, BK=16, micro 8x4) + RoPE
//   blocks 128..255 -> bias GEMM (64 rows, k-chunk 32, smem 10.75KB)
// Dynamic smem = proj layout: (16*68 + 16*128)*4 = 12544 B (bias fits inside).
// =====================================================================

__device__ __forceinline__ void proj_body(float* smem,
                                          const float* __restrict__ X,
                                          const float* __restrict__ w1,
                                          const float* __restrict__ b1,
                                          int blk)
{
    float* As = smem;               // [16][68]  (k-major, padded)
    float* Bs = smem + 16 * 68;     // [16][128]

    const int tid = threadIdx.x;
    const int rowBase = blk * 64;

    const int lm = tid >> 2;            // 0..63
    const int lk = (tid & 3) << 2;      // 0,4,8,12
    const float* Xrow = X + (size_t)(rowBase + lm) * HID + lk;

    const int nthr = tid & 31;          // pair index i
    const int mthr = tid >> 5;
    const int n0 = nthr << 2;
    const int m0 = mthr << 3;

    float acc[8][4];
#pragma unroll
    for (int mi = 0; mi < 8; ++mi)
#pragma unroll
        for (int ni = 0; ni < 4; ++ni) acc[mi][ni] = 0.f;

    const int wi0 = tid, wi1 = tid + 256;
    float4 xa  = *(const float4*)(Xrow);
    float4 wv0 = *(const float4*)&w1[(wi0 >> 5) * 128 + (wi0 & 31) * 4];
    float4 wv1 = *(const float4*)&w1[(wi1 >> 5) * 128 + (wi1 & 31) * 4];

    for (int kc = 0; kc < HID / 16; ++kc) {
        __syncthreads();
        As[(lk + 0) * 68 + lm] = xa.x;
        As[(lk + 1) * 68 + lm] = xa.y;
        As[(lk + 2) * 68 + lm] = xa.z;
        As[(lk + 3) * 68 + lm] = xa.w;
        *(float4*)&Bs[(wi0 >> 5) * 128 + (wi0 & 31) * 4] = wv0;
        *(float4*)&Bs[(wi1 >> 5) * 128 + (wi1 & 31) * 4] = wv1;
        __syncthreads();

        if (kc + 1 < HID / 16) {
            xa  = *(const float4*)(Xrow + (kc + 1) * 16);
            wv0 = *(const float4*)&w1[((kc + 1) * 16 + (wi0 >> 5)) * 128 + (wi0 & 31) * 4];
            wv1 = *(const float4*)&w1[((kc + 1) * 16 + (wi1 >> 5)) * 128 + (wi1 & 31) * 4];
        }

#pragma unroll
        for (int kk = 0; kk < 16; ++kk) {
            float4 a0 = *(const float4*)(&As[kk * 68 + m0]);
            float4 a1 = *(const float4*)(&As[kk * 68 + m0 + 4]);
            float4 bv = *(const float4*)(&Bs[kk * 128 + n0]);
            float am[8] = {a0.x, a0.y, a0.z, a0.w, a1.x, a1.y, a1.z, a1.w};
            float bn[4] = {bv.x, bv.y, bv.z, bv.w};
#pragma unroll
            for (int mi = 0; mi < 8; ++mi)
#pragma unroll
                for (int ni = 0; ni < 4; ++ni)
                    acc[mi][ni] = fmaf(am[mi], bn[ni], acc[mi][ni]);
        }
    }

    const int i = nthr;
    const float invf = powf(10000.0f, -(float)i * (1.0f / 32.0f));
    const float4 b1v = *(const float4*)&b1[n0];

#pragma unroll
    for (int mi = 0; mi < 8; ++mi) {
        const int r = rowBase + m0 + mi;
        const int pos = r & (SEQ - 1);
        float sv, cv;
        sincosf((float)pos * invf, &sv, &cv);
        const float q0 = acc[mi][0] + b1v.x;   // proj col 4i   -> q[2i]
        const float k0 = acc[mi][1] + b1v.y;   // proj col 4i+1 -> k[2i]
        const float q1 = acc[mi][2] + b1v.z;   // proj col 4i+2 -> q[2i+1]
        const float k1 = acc[mi][3] + b1v.w;   // proj col 4i+3 -> k[2i+1]
        float2 qo = make_float2(fmaf(q0, cv, -q1 * sv), fmaf(q1, cv, q0 * sv));
        float2 ko = make_float2(fmaf(k0, cv, -k1 * sv), fmaf(k1, cv, k0 * sv));
        ((float2*)g_q)[(r << 5) + i] = qo;
        ((float2*)g_k)[(r << 5) + i] = ko;
    }
}

// bias: 64 rows/block, k chunked by 32, coalesced X/w2 staging through smem.
// Thread tid = 4*r + s  (r = row 0..63, s = k-split 0..3, splits = adjacent lanes).
__device__ __forceinline__ void bias_body(float* smem,
                                          const float* __restrict__ X,
                                          const float* __restrict__ w2,
                                          const float* __restrict__ b2,
                                          int blk)
{
    float* sA = smem;                 // [64][33]  (2112 floats)
    float* sW = smem + 64 * 33;       // [32][18]  (576 floats)

    const int tid = threadIdx.x;
    const int r = tid >> 2;           // row in tile
    const int s = tid & 3;            // k-split
    const int rowBase = blk * 64;

    float acc[18];
#pragma unroll
    for (int e = 0; e < 18; ++e) acc[e] = 0.f;

    for (int kc = 0; kc < HID / 32; ++kc) {
        __syncthreads();
        // stage X chunk: 64 rows x 32 k, float4-coalesced
        for (int i = tid; i < 512; i += 256) {
            int rr = i >> 3, j4 = (i & 7) << 2;
            float4 v = *(const float4*)&X[(size_t)(rowBase + rr) * HID + kc * 32 + j4];
            sA[rr * 33 + j4 + 0] = v.x;
            sA[rr * 33 + j4 + 1] = v.y;
            sA[rr * 33 + j4 + 2] = v.z;
            sA[rr * 33 + j4 + 3] = v.w;
        }
        // stage w2 chunk: 32 k x 18 e, fully coalesced
        for (int i = tid; i < 576; i += 256)
            sW[i] = w2[kc * 32 * 18 + i];
        __syncthreads();

#pragma unroll
        for (int kk = 0; kk < 8; ++kk) {
            const float xv = sA[r * 33 + s * 8 + kk];
            const float* wr = &sW[(s * 8 + kk) * 18];
#pragma unroll
            for (int e2 = 0; e2 < 9; ++e2) {
                float2 wv = *(const float2*)&wr[e2 * 2];
                acc[e2 * 2 + 0] = fmaf(xv, wv.x, acc[e2 * 2 + 0]);
                acc[e2 * 2 + 1] = fmaf(xv, wv.y, acc[e2 * 2 + 1]);
            }
        }
    }

    // reduce the 4 k-splits (adjacent lanes)
#pragma unroll
    for (int e = 0; e < 18; ++e) {
        acc[e] += __shfl_xor_sync(0xffffffffu, acc[e], 1);
        acc[e] += __shfl_xor_sync(0xffffffffu, acc[e], 2);
    }

    if (s == 0) {
        const int row = rowBase + r;
        const int bb = row >> 10, nn = row & (SEQ - 1);
#pragma unroll
        for (int e = 0; e < 18; ++e) {
            const float val = (acc[e] + b2[e]) * 0.5f;
            const int h = e >> 1;
            if ((e & 1) == 0) g_be[(bb * ENT + h) * SEQ + nn] = val;
            else              g_bo[(bb * ENT + h) * SEQ + nn] = val;
        }
    }
}

__global__ __launch_bounds__(256) void k_projbias(const float* __restrict__ X,
                                                  const float* __restrict__ w1,
                                                  const float* __restrict__ b1,
                                                  const float* __restrict__ w2,
                                                  const float* __restrict__ b2)
{
    extern __shared__ __align__(16) float smem[];
    const int bx = blockIdx.x;
    if (bx < 128) proj_body(smem, X, w1, b1, bx);
    else          bias_body(smem, X, w2, b2, bx - 128);
}

// =====================================================================
// Kernel B: out[b,e,m,n] = (qk/8)*mr*mc + (negr*mc + negc + tril) + mr*mc*(be+bo)
// Tile: 128m x 64n, 256 threads, micro-tile 8m x 4n. Streaming stores (__stcs).
// =====================================================================
__global__ __launch_bounds__(256, 3) void k_out(const float* __restrict__ mask,
                                                float* __restrict__ out)
{
    __shared__ __align__(16) float qt[32 * 132];  // [d][m], stride 132
    __shared__ __align__(16) float kt[32 * 68];   // [d][n], stride 68
    __shared__ __align__(16) float bes[ENT * 64];
    __shared__ __align__(16) float bos[ENT * 128];
    __shared__ __align__(16) float mrow[128];
    __shared__ __align__(16) float mcol[64];

    const int tid = threadIdx.x;
    const int nBase = blockIdx.x * 64;
    const int mBase = blockIdx.y * 128;
    const int b = blockIdx.z;
    const int bOff = b * SEQ;

    const int n0 = (tid & 15) << 2;               // 0..60
    const int m0 = (tid >> 4) << 3;               // 0..120

    for (int i = tid; i < ENT * 64; i += 256)
        bes[i] = g_be[(b * ENT + (i >> 6)) * SEQ + nBase + (i & 63)];
    for (int i = tid; i < ENT * 128; i += 256)
        bos[i] = g_bo[(b * ENT + (i >> 7)) * SEQ + mBase + (i & 127)];
    for (int i = tid; i < 128; i += 256) mrow[i] = mask[b * SEQ + mBase + i];
    if (tid < 64) mcol[tid] = mask[b * SEQ + nBase + tid];

    float acc[8][4];
#pragma unroll
    for (int mi = 0; mi < 8; ++mi)
#pragma unroll
        for (int ni = 0; ni < 4; ++ni) acc[mi][ni] = 0.f;

    for (int ch = 0; ch < 2; ++ch) {
        __syncthreads();
        // q tile transposed: m-fast mapping -> conflict-free STS
        for (int i = tid; i < 128 * 8; i += 256) {
            int m = i & 127, d4 = (i >> 7) << 2;
            float4 v = *(const float4*)&g_q[((size_t)(bOff + mBase + m) << 6) + ch * 32 + d4];
            qt[(d4 + 0) * 132 + m] = v.x;
            qt[(d4 + 1) * 132 + m] = v.y;
            qt[(d4 + 2) * 132 + m] = v.z;
            qt[(d4 + 3) * 132 + m] = v.w;
        }
        // k tile transposed: n-fast mapping
        for (int i = tid; i < 64 * 8; i += 256) {
            int n = i & 63, d4 = (i >> 6) << 2;
            float4 v = *(const float4*)&g_k[((size_t)(bOff + nBase + n) << 6) + ch * 32 + d4];
            kt[(d4 + 0) * 68 + n] = v.x;
            kt[(d4 + 1) * 68 + n] = v.y;
            kt[(d4 + 2) * 68 + n] = v.z;
            kt[(d4 + 3) * 68 + n] = v.w;
        }
        __syncthreads();

#pragma unroll 8
        for (int d = 0; d < 32; ++d) {
            float4 kv = *(const float4*)&kt[d * 68 + n0];
            float4 q0 = *(const float4*)&qt[d * 132 + m0];
            float4 q1 = *(const float4*)&qt[d * 132 + m0 + 4];
            float qv[8] = {q0.x, q0.y, q0.z, q0.w, q1.x, q1.y, q1.z, q1.w};
#pragma unroll
            for (int mi = 0; mi < 8; ++mi) {
                acc[mi][0] = fmaf(qv[mi], kv.x, acc[mi][0]);
                acc[mi][1] = fmaf(qv[mi], kv.y, acc[mi][1]);
                acc[mi][2] = fmaf(qv[mi], kv.z, acc[mi][2]);
                acc[mi][3] = fmaf(qv[mi], kv.w, acc[mi][3]);
            }
        }
    }

    // ---- epilogue: fold scale, masks, tril into acc ----
    float mr[8];
#pragma unroll
    for (int mi = 0; mi < 8; ++mi) mr[mi] = mrow[m0 + mi];
    float4 mcv = *(const float4*)&mcol[n0];
    float mcs[4] = {mcv.x, mcv.y, mcv.z, mcv.w};

#pragma unroll
    for (int mi = 0; mi < 8; ++mi) {
        const float negr = -NEGC * (1.0f - mr[mi]);
        const int m = mBase + m0 + mi;
#pragma unroll
        for (int ni = 0; ni < 4; ++ni) {
            const float mc = mcs[ni];
            const float negc = -NEGC * (1.0f - mc);
            const int n = nBase + n0 + ni;
            const float t = (n < m) ? -NEGC : 0.0f;
            const float p = acc[mi][ni] * 0.125f * mr[mi];
            acc[mi][ni] = fmaf(p, mc, fmaf(negr, mc, negc + t));
        }
    }

    // ---- 9 output planes, streaming stores ----
#pragma unroll
    for (int e = 0; e < ENT; ++e) {
        float4 bev = *(const float4*)&bes[e * 64 + n0];
        float beA[4] = {bev.x, bev.y, bev.z, bev.w};
        const size_t planeRow = (size_t)(b * ENT + e) << 10;
#pragma unroll
        for (int mi = 0; mi < 8; ++mi) {
            const float bo = bos[e * 128 + m0 + mi];
            const float c1 = mr[mi] * bo;
            float4 o;
            o.x = fmaf(mcs[0], fmaf(mr[mi], beA[0], c1), acc[mi][0]);
            o.y = fmaf(mcs[1], fmaf(mr[mi], beA[1], c1), acc[mi][1]);
            o.z = fmaf(mcs[2], fmaf(mr[mi], beA[2], c1), acc[mi][2]);
            o.w = fmaf(mcs[3], fmaf(mr[mi], beA[3], c1), acc[mi][3]);
            __stcs((float4*)&out[((planeRow + mBase + m0 + mi) << 10) + nBase + n0], o);
        }
    }
}

// =====================================================================
extern "C" void kernel_launch(void* const* d_in, const int* in_sizes, int n_in,
                              void* d_out, int out_size)
{
    const float* X    = (const float*)d_in[0];   // (8,1024,768)
    const float* mask = (const float*)d_in[1];   // (8,1024)
    const float* w1   = (const float*)d_in[2];   // (768,128)
    const float* b1   = (const float*)d_in[3];   // (128,)
    const float* w2   = (const float*)d_in[4];   // (768,18)
    const float* b2   = (const float*)d_in[5];   // (18,)
    float* out = (float*)d_out;                  // (8,9,1024,1024)

    // dynamic smem = proj layout: (16*68 + 16*128) floats = 12544 B
    const int smemBytes = (16 * 68 + 16 * 128) * 4;
    k_projbias<<<256, 256, smemBytes>>>(X, w1, b1, w2, b2);
    k_out<<<dim3(16, 8, 8), 256>>>(mask, out);
}

// round 8
// speedup vs baseline: 1.1516x; 1.0423x over previous
#include <cuda_runtime.h>
#include <math.h>

#define BATCH 8
#define SEQ   1024
#define HID   768
#define INNER 64
#define ENT   9
#define NEGC  1000000000000.0f

typedef unsigned long long ull;

// ---------------- f32x2 helpers (FFMA2 path, sm_100+) ----------------
__device__ __forceinline__ ull pack2(float lo, float hi) {
    ull r;
    asm("mov.b64 %0, {%1, %2};" : "=l"(r)
        : "r"(__float_as_uint(lo)), "r"(__float_as_uint(hi)));
    return r;
}
__device__ __forceinline__ ull bcast2(float v) { return pack2(v, v); }
__device__ __forceinline__ void unpack2(ull v, float& lo, float& hi) {
    unsigned int a, b;
    asm("mov.b64 {%0, %1}, %2;" : "=r"(a), "=r"(b) : "l"(v));
    lo = __uint_as_float(a);
    hi = __uint_as_float(b);
}
__device__ __forceinline__ ull ffma2(ull a, ull b, ull c) {
    ull d;
    asm("fma.rn.f32x2 %0, %1, %2, %3;" : "=l"(d) : "l"(a), "l"(b), "l"(c));
    return d;
}

// ---------------- scratch (device globals; no allocation allowed) ----------------
__device__ float g_q[BATCH * SEQ * INNER];       // rope'd q, [row][64]
__device__ float g_k[BATCH * SEQ * INNER];       // rope'd k, [row][64]
__device__ float g_be[BATCH * ENT * SEQ];        // bias even (col/n bias)
__device__ float g_bo[BATCH * ENT * SEQ];        // bias odd  (row/m bias)

// =====================================================================
// Fused Kernel A:
//   blocks 0..127   -> proj GEMM (BM=64, BN=128, BK=16, micro 8x4, FFMA2) + RoPE
//   blocks 128..255 -> bias GEMM (64 rows, k-chunk 32)
// Dynamic smem = proj layout: (16*68 + 16*128)*4 = 12544 B.
// =====================================================================

__device__ __forceinline__ void proj_body(float* smem,
                                          const float* __restrict__ X,
                                          const float* __restrict__ w1,
                                          const float* __restrict__ b1,
                                          int blk)
{
    float* As = smem;               // [16][68]  (k-major, padded)
    float* Bs = smem + 16 * 68;     // [16][128]

    const int tid = threadIdx.x;
    const int rowBase = blk * 64;

    const int lm = tid >> 2;            // 0..63
    const int lk = (tid & 3) << 2;      // 0,4,8,12
    const float* Xrow = X + (size_t)(rowBase + lm) * HID + lk;

    const int nthr = tid & 31;          // pair index i
    const int mthr = tid >> 5;
    const int n0 = nthr << 2;
    const int m0 = mthr << 3;

    // acc2[mp][ni]: fp32 pair over (m0+2mp, m0+2mp+1), column n0+ni
    ull acc2[4][4];
#pragma unroll
    for (int mp = 0; mp < 4; ++mp)
#pragma unroll
        for (int ni = 0; ni < 4; ++ni) acc2[mp][ni] = 0ull;

    const int wi0 = tid, wi1 = tid + 256;
    float4 xa  = *(const float4*)(Xrow);
    float4 wv0 = *(const float4*)&w1[(wi0 >> 5) * 128 + (wi0 & 31) * 4];
    float4 wv1 = *(const float4*)&w1[(wi1 >> 5) * 128 + (wi1 & 31) * 4];

    for (int kc = 0; kc < HID / 16; ++kc) {
        __syncthreads();
        As[(lk + 0) * 68 + lm] = xa.x;
        As[(lk + 1) * 68 + lm] = xa.y;
        As[(lk + 2) * 68 + lm] = xa.z;
        As[(lk + 3) * 68 + lm] = xa.w;
        *(float4*)&Bs[(wi0 >> 5) * 128 + (wi0 & 31) * 4] = wv0;
        *(float4*)&Bs[(wi1 >> 5) * 128 + (wi1 & 31) * 4] = wv1;
        __syncthreads();

        if (kc + 1 < HID / 16) {
            xa  = *(const float4*)(Xrow + (kc + 1) * 16);
            wv0 = *(const float4*)&w1[((kc + 1) * 16 + (wi0 >> 5)) * 128 + (wi0 & 31) * 4];
            wv1 = *(const float4*)&w1[((kc + 1) * 16 + (wi1 >> 5)) * 128 + (wi1 & 31) * 4];
        }

#pragma unroll
        for (int kk = 0; kk < 16; ++kk) {
            // a pairs read directly as 64-bit lanes (m0 is 8-float aligned)
            ulonglong2 A0 = *(const ulonglong2*)(&As[kk * 68 + m0]);
            ulonglong2 A1 = *(const ulonglong2*)(&As[kk * 68 + m0 + 4]);
            float4 bv = *(const float4*)(&Bs[kk * 128 + n0]);
            ull ap[4] = {A0.x, A0.y, A1.x, A1.y};
            ull bb[4] = {bcast2(bv.x), bcast2(bv.y), bcast2(bv.z), bcast2(bv.w)};
#pragma unroll
            for (int mp = 0; mp < 4; ++mp)
#pragma unroll
                for (int ni = 0; ni < 4; ++ni)
                    acc2[mp][ni] = ffma2(ap[mp], bb[ni], acc2[mp][ni]);
        }
    }

    const int i = nthr;
    const float invf = powf(10000.0f, -(float)i * (1.0f / 32.0f));
    const float4 b1v = *(const float4*)&b1[n0];

#pragma unroll
    for (int mp = 0; mp < 4; ++mp) {
        float c0lo, c0hi, c1lo, c1hi, c2lo, c2hi, c3lo, c3hi;
        unpack2(acc2[mp][0], c0lo, c0hi);
        unpack2(acc2[mp][1], c1lo, c1hi);
        unpack2(acc2[mp][2], c2lo, c2hi);
        unpack2(acc2[mp][3], c3lo, c3hi);
        float cA[2][4] = {{c0lo, c1lo, c2lo, c3lo}, {c0hi, c1hi, c2hi, c3hi}};
#pragma unroll
        for (int h = 0; h < 2; ++h) {
            const int r = rowBase + m0 + 2 * mp + h;
            const int pos = r & (SEQ - 1);
            float sv, cv;
            sincosf((float)pos * invf, &sv, &cv);
            const float q0 = cA[h][0] + b1v.x;   // proj col 4i   -> q[2i]
            const float k0 = cA[h][1] + b1v.y;   // proj col 4i+1 -> k[2i]
            const float q1 = cA[h][2] + b1v.z;   // proj col 4i+2 -> q[2i+1]
            const float k1 = cA[h][3] + b1v.w;   // proj col 4i+3 -> k[2i+1]
            float2 qo = make_float2(fmaf(q0, cv, -q1 * sv), fmaf(q1, cv, q0 * sv));
            float2 ko = make_float2(fmaf(k0, cv, -k1 * sv), fmaf(k1, cv, k0 * sv));
            ((float2*)g_q)[(r << 5) + i] = qo;
            ((float2*)g_k)[(r << 5) + i] = ko;
        }
    }
}

// bias: 64 rows/block, k chunked by 32, coalesced X/w2 staging through smem.
__device__ __forceinline__ void bias_body(float* smem,
                                          const float* __restrict__ X,
                                          const float* __restrict__ w2,
                                          const float* __restrict__ b2,
                                          int blk)
{
    float* sA = smem;                 // [64][33]
    float* sW = smem + 64 * 33;       // [32][18]

    const int tid = threadIdx.x;
    const int r = tid >> 2;           // row in tile
    const int s = tid & 3;            // k-split
    const int rowBase = blk * 64;

    float acc[18];
#pragma unroll
    for (int e = 0; e < 18; ++e) acc[e] = 0.f;

    for (int kc = 0; kc < HID / 32; ++kc) {
        __syncthreads();
        for (int i = tid; i < 512; i += 256) {
            int rr = i >> 3, j4 = (i & 7) << 2;
            float4 v = *(const float4*)&X[(size_t)(rowBase + rr) * HID + kc * 32 + j4];
            sA[rr * 33 + j4 + 0] = v.x;
            sA[rr * 33 + j4 + 1] = v.y;
            sA[rr * 33 + j4 + 2] = v.z;
            sA[rr * 33 + j4 + 3] = v.w;
        }
        for (int i = tid; i < 576; i += 256)
            sW[i] = w2[kc * 32 * 18 + i];
        __syncthreads();

#pragma unroll
        for (int kk = 0; kk < 8; ++kk) {
            const float xv = sA[r * 33 + s * 8 + kk];
            const float* wr = &sW[(s * 8 + kk) * 18];
#pragma unroll
            for (int e2 = 0; e2 < 9; ++e2) {
                float2 wv = *(const float2*)&wr[e2 * 2];
                acc[e2 * 2 + 0] = fmaf(xv, wv.x, acc[e2 * 2 + 0]);
                acc[e2 * 2 + 1] = fmaf(xv, wv.y, acc[e2 * 2 + 1]);
            }
        }
    }

#pragma unroll
    for (int e = 0; e < 18; ++e) {
        acc[e] += __shfl_xor_sync(0xffffffffu, acc[e], 1);
        acc[e] += __shfl_xor_sync(0xffffffffu, acc[e], 2);
    }

    if (s == 0) {
        const int row = rowBase + r;
        const int bb = row >> 10, nn = row & (SEQ - 1);
#pragma unroll
        for (int e = 0; e < 18; ++e) {
            const float val = (acc[e] + b2[e]) * 0.5f;
            const int h = e >> 1;
            if ((e & 1) == 0) g_be[(bb * ENT + h) * SEQ + nn] = val;
            else              g_bo[(bb * ENT + h) * SEQ + nn] = val;
        }
    }
}

__global__ __launch_bounds__(256) void k_projbias(const float* __restrict__ X,
                                                  const float* __restrict__ w1,
                                                  const float* __restrict__ b1,
                                                  const float* __restrict__ w2,
                                                  const float* __restrict__ b2)
{
    extern __shared__ __align__(16) float smem[];
    const int bx = blockIdx.x;
    if (bx < 128) proj_body(smem, X, w1, b1, bx);
    else          bias_body(smem, X, w2, b2, bx - 128);
}

// =====================================================================
// Kernel B: out[b,e,m,n] = (qk/8)*mr*mc + (negr*mc + negc + tril) + mr*mc*(be+bo)
// Tile: 128m x 64n, 256 threads, micro-tile 8m x 4n, FFMA2 mainloop.
// =====================================================================
__global__ __launch_bounds__(256, 3) void k_out(const float* __restrict__ mask,
                                                float* __restrict__ out)
{
    __shared__ __align__(16) float qt[32 * 132];  // [d][m], stride 132
    __shared__ __align__(16) float kt[32 * 68];   // [d][n], stride 68
    __shared__ __align__(16) float bes[ENT * 64];
    __shared__ __align__(16) float bos[ENT * 128];
    __shared__ __align__(16) float mrow[128];
    __shared__ __align__(16) float mcol[64];

    const int tid = threadIdx.x;
    const int nBase = blockIdx.x * 64;
    const int mBase = blockIdx.y * 128;
    const int b = blockIdx.z;
    const int bOff = b * SEQ;

    const int n0 = (tid & 15) << 2;               // 0..60
    const int m0 = (tid >> 4) << 3;               // 0..120

    for (int i = tid; i < ENT * 64; i += 256)
        bes[i] = g_be[(b * ENT + (i >> 6)) * SEQ + nBase + (i & 63)];
    for (int i = tid; i < ENT * 128; i += 256)
        bos[i] = g_bo[(b * ENT + (i >> 7)) * SEQ + mBase + (i & 127)];
    for (int i = tid; i < 128; i += 256) mrow[i] = mask[b * SEQ + mBase + i];
    if (tid < 64) mcol[tid] = mask[b * SEQ + nBase + tid];

    // acc2[mp][ni]: pair over (m0+2mp, m0+2mp+1)
    ull acc2[4][4];
#pragma unroll
    for (int mp = 0; mp < 4; ++mp)
#pragma unroll
        for (int ni = 0; ni < 4; ++ni) acc2[mp][ni] = 0ull;

    for (int ch = 0; ch < 2; ++ch) {
        __syncthreads();
        // q tile transposed: m-fast mapping -> conflict-free STS
        for (int i = tid; i < 128 * 8; i += 256) {
            int m = i & 127, d4 = (i >> 7) << 2;
            float4 v = *(const float4*)&g_q[((size_t)(bOff + mBase + m) << 6) + ch * 32 + d4];
            qt[(d4 + 0) * 132 + m] = v.x;
            qt[(d4 + 1) * 132 + m] = v.y;
            qt[(d4 + 2) * 132 + m] = v.z;
            qt[(d4 + 3) * 132 + m] = v.w;
        }
        // k tile transposed: n-fast mapping
        for (int i = tid; i < 64 * 8; i += 256) {
            int n = i & 63, d4 = (i >> 6) << 2;
            float4 v = *(const float4*)&g_k[((size_t)(bOff + nBase + n) << 6) + ch * 32 + d4];
            kt[(d4 + 0) * 68 + n] = v.x;
            kt[(d4 + 1) * 68 + n] = v.y;
            kt[(d4 + 2) * 68 + n] = v.z;
            kt[(d4 + 3) * 68 + n] = v.w;
        }
        __syncthreads();

#pragma unroll 8
        for (int d = 0; d < 32; ++d) {
            float4 kv = *(const float4*)&kt[d * 68 + n0];
            // q pairs read directly as 64-bit lanes (m0 is 8-float aligned, qt stride 132 floats keeps 8B alignment for even m0)
            ulonglong2 Q0 = *(const ulonglong2*)&qt[d * 132 + m0];
            ulonglong2 Q1 = *(const ulonglong2*)&qt[d * 132 + m0 + 4];
            ull qp[4] = {Q0.x, Q0.y, Q1.x, Q1.y};
            ull kb[4] = {bcast2(kv.x), bcast2(kv.y), bcast2(kv.z), bcast2(kv.w)};
#pragma unroll
            for (int mp = 0; mp < 4; ++mp)
#pragma unroll
                for (int ni = 0; ni < 4; ++ni)
                    acc2[mp][ni] = ffma2(qp[mp], kb[ni], acc2[mp][ni]);
        }
    }

    // ---- unpack pairs -> accf[8][4] ----
    float accf[8][4];
#pragma unroll
    for (int mp = 0; mp < 4; ++mp)
#pragma unroll
        for (int ni = 0; ni < 4; ++ni)
            unpack2(acc2[mp][ni], accf[2 * mp][ni], accf[2 * mp + 1][ni]);

    // ---- epilogue: fold scale, masks, tril ----
    float mr[8];
#pragma unroll
    for (int mi = 0; mi < 8; ++mi) mr[mi] = mrow[m0 + mi];
    float4 mcv = *(const float4*)&mcol[n0];
    float mcs[4] = {mcv.x, mcv.y, mcv.z, mcv.w};

#pragma unroll
    for (int mi = 0; mi < 8; ++mi) {
        const float negr = -NEGC * (1.0f - mr[mi]);
        const int m = mBase + m0 + mi;
#pragma unroll
        for (int ni = 0; ni < 4; ++ni) {
            const float mc = mcs[ni];
            const float negc = -NEGC * (1.0f - mc);
            const int n = nBase + n0 + ni;
            const float t = (n < m) ? -NEGC : 0.0f;
            const float p = accf[mi][ni] * 0.125f * mr[mi];
            accf[mi][ni] = fmaf(p, mc, fmaf(negr, mc, negc + t));
        }
    }

    // ---- 9 output planes, streaming stores ----
#pragma unroll
    for (int e = 0; e < ENT; ++e) {
        float4 bev = *(const float4*)&bes[e * 64 + n0];
        float beA[4] = {bev.x, bev.y, bev.z, bev.w};
        const size_t planeRow = (size_t)(b * ENT + e) << 10;
#pragma unroll
        for (int mi = 0; mi < 8; ++mi) {
            const float bo = bos[e * 128 + m0 + mi];
            const float c1 = mr[mi] * bo;
            float4 o;
            o.x = fmaf(mcs[0], fmaf(mr[mi], beA[0], c1), accf[mi][0]);
            o.y = fmaf(mcs[1], fmaf(mr[mi], beA[1], c1), accf[mi][1]);
            o.z = fmaf(mcs[2], fmaf(mr[mi], beA[2], c1), accf[mi][2]);
            o.w = fmaf(mcs[3], fmaf(mr[mi], beA[3], c1), accf[mi][3]);
            __stcs((float4*)&out[((planeRow + mBase + m0 + mi) << 10) + nBase + n0], o);
        }
    }
}

// =====================================================================
extern "C" void kernel_launch(void* const* d_in, const int* in_sizes, int n_in,
                              void* d_out, int out_size)
{
    const float* X    = (const float*)d_in[0];   // (8,1024,768)
    const float* mask = (const float*)d_in[1];   // (8,1024)
    const float* w1   = (const float*)d_in[2];   // (768,128)
    const float* b1   = (const float*)d_in[3];   // (128,)
    const float* w2   = (const float*)d_in[4];   // (768,18)
    const float* b2   = (const float*)d_in[5];   // (18,)
    float* out = (float*)d_out;                  // (8,9,1024,1024)

    const int smemBytes = (16 * 68 + 16 * 128) * 4;   // 12544 B
    k_projbias<<<256, 256, smemBytes>>>(X, w1, b1, w2, b2);
    k_out<<<dim3(16, 8, 8), 256>>>(mask, out);
}